// round 7
// baseline (speedup 1.0000x reference)
#include <cuda_runtime.h>
#include <cuda_bf16.h>
#include <cstdint>

#define NB   2
#define SEQ  2048
#define DIM  1024
#define NH   16
#define HD   64
#define MROWS (NB*SEQ)   // 4096

// ---------------------------------------------------------------------------
// Scratch (allocation-free rule: __device__ globals).
// NOTE: these are referenced ONLY from device code — passing a __device__
// symbol as a host-side kernel argument is UB and was the R5/R6 bug.
// ---------------------------------------------------------------------------
__device__ float g_q[NB*NH*SEQ*HD];     // [B,H,S,hd] fp32 (attention operands)
__device__ float g_k[NB*NH*SEQ*HD];
__device__ float g_v[NB*NH*SEQ*HD];
__device__ __nv_bfloat16 g_ihi[MROWS*DIM];   // GEMM A operand, hi split
__device__ __nv_bfloat16 g_ilo[MROWS*DIM];   // GEMM A operand, lo split
__device__ __nv_bfloat16 g_whi[DIM*DIM];     // GEMM W operand, hi split
__device__ __nv_bfloat16 g_wlo[DIM*DIM];     // GEMM W operand, lo split
__device__ float g_cos[SEQ*(HD/2)];
__device__ float g_sin[SEQ*(HD/2)];

// ---------------------------------------------------------------------------
// Baseline-PTX helpers (compute_103-safe)
// ---------------------------------------------------------------------------
__device__ __forceinline__ uint32_t smem_u32(const void* p) {
    uint32_t a;
    asm("{ .reg .u64 t; cvta.to.shared.u64 t, %1; cvt.u32.u64 %0, t; }" : "=r"(a) : "l"(p));
    return a;
}
__device__ __forceinline__ void cp16(uint32_t dst, const void* src) {
    asm volatile("cp.async.cg.shared.global [%0], [%1], 16;"
                 :: "r"(dst), "l"(__cvta_generic_to_global(src)) : "memory");
}
#define CP_COMMIT() asm volatile("cp.async.commit_group;" ::: "memory")
#define CP_WAIT(n)  asm volatile("cp.async.wait_group %0;" :: "n"(n) : "memory")

__device__ __forceinline__ uint32_t lds32(uint32_t a) {
    uint32_t v;
    asm volatile("ld.shared.b32 %0, [%1];" : "=r"(v) : "r"(a));
    return v;
}
__device__ __forceinline__ void mma16816(float* c, const uint32_t* a, uint32_t b0, uint32_t b1) {
    asm volatile("mma.sync.aligned.m16n8k16.row.col.f32.bf16.bf16.f32 "
                 "{%0,%1,%2,%3}, {%4,%5,%6,%7}, {%8,%9}, {%0,%1,%2,%3};"
                 : "+f"(c[0]), "+f"(c[1]), "+f"(c[2]), "+f"(c[3])
                 : "r"(a[0]), "r"(a[1]), "r"(a[2]), "r"(a[3]), "r"(b0), "r"(b1));
}

// Blackwell packed fp32-pair ops for the SIMT attention kernel
__device__ __forceinline__ void f2fma(float2& c, float2 a, float2 b) {
    unsigned long long cc = *reinterpret_cast<unsigned long long*>(&c);
    unsigned long long aa = *reinterpret_cast<unsigned long long*>(&a);
    unsigned long long bb = *reinterpret_cast<unsigned long long*>(&b);
    asm("fma.rn.f32x2 %0, %1, %2, %0;" : "+l"(cc) : "l"(aa), "l"(bb));
    c = *reinterpret_cast<float2*>(&cc);
}
__device__ __forceinline__ void f2mul(float2& c, float2 a) {
    unsigned long long cc = *reinterpret_cast<unsigned long long*>(&c);
    unsigned long long aa = *reinterpret_cast<unsigned long long*>(&a);
    asm("mul.rn.f32x2 %0, %0, %1;" : "+l"(cc) : "l"(aa));
    c = *reinterpret_cast<float2*>(&cc);
}

// ---------------------------------------------------------------------------
// RoPE table
// ---------------------------------------------------------------------------
__global__ void rope_table_kernel() {
    int i = blockIdx.x * blockDim.x + threadIdx.x;
    if (i >= SEQ * (HD/2)) return;
    int s = i >> 5;
    int p = i & 31;
    double inv = pow(10000.0, -(double)p / 32.0);
    double a = (double)s * inv;
    g_cos[i] = (float)cos(a);
    g_sin[i] = (float)sin(a);
}

// ---------------------------------------------------------------------------
// fp32 -> (hi, lo) bf16 split: x = hi + lo + O(2^-18 x)
// DST=0 -> g_ihi/g_ilo (input operand), DST=1 -> g_whi/g_wlo (weight operand)
// ---------------------------------------------------------------------------
template<int DST>
__global__ void cvt_split(const float* __restrict__ x, int n4) {
    int i = blockIdx.x * blockDim.x + threadIdx.x;
    if (i >= n4) return;
    __nv_bfloat16* hi = (DST == 0) ? g_ihi : g_whi;
    __nv_bfloat16* lo = (DST == 0) ? g_ilo : g_wlo;
    float4 v = ((const float4*)x)[i];
    __nv_bfloat16 h0 = __float2bfloat16(v.x), h1 = __float2bfloat16(v.y);
    __nv_bfloat16 h2 = __float2bfloat16(v.z), h3 = __float2bfloat16(v.w);
    __nv_bfloat162 H01, H23, L01, L23;
    H01.x = h0; H01.y = h1; H23.x = h2; H23.y = h3;
    L01.x = __float2bfloat16(v.x - __bfloat162float(h0));
    L01.y = __float2bfloat16(v.y - __bfloat162float(h1));
    L23.x = __float2bfloat16(v.z - __bfloat162float(h2));
    L23.y = __float2bfloat16(v.w - __bfloat162float(h3));
    ((__nv_bfloat162*)hi)[2*i]   = H01;
    ((__nv_bfloat162*)hi)[2*i+1] = H23;
    ((__nv_bfloat162*)lo)[2*i]   = L01;
    ((__nv_bfloat162*)lo)[2*i+1] = L23;
}

// ---------------------------------------------------------------------------
// mma.sync NT GEMM: C[m,n] = sum_k A[m,k]*W[n,k] + bias[n], 3-term bf16 split.
// Operands read from g_ihi/g_ilo (A) and g_whi/g_wlo (W) device globals.
// CTA 128x128, 8 warps (2x4), warp tile 64x32, BK=32, 2-stage cp.async.
// Fragments via explicit per-lane ld.shared.b32 (PTX fragment tables):
//   A  (m16n8k16 .row): a0=(m0+l/4, k0+(l%4)*2) a1=row+8 a2=col+8 a3=both
//   B  (.col, W[n][k]): b0=(n0+l/4, k0+(l%4)*2) b1=col+8
//   C: c0,c1=(m0+l/4, n0+(l%4)*2,+1), c2,c3=row+8
// Smem rows padded to 40 bf16 (80B) -> conflict-free b32 access.
// MODE 0/1: Q/K proj (+RoPE, scatter [B,H,S,hd]); 2: V; 3: O proj to Cout.
// ---------------------------------------------------------------------------
#define BK        32
#define ROWPAD    40                    // bf16 elems per smem row
#define OPBUF_B   (128*ROWPAD*2)        // 10240 bytes per operand buffer
#define STAGE_B   (4*OPBUF_B)           // 40960 bytes per stage
#define SMEM_B    (2*STAGE_B)           // 81920 bytes total

template<int MODE>
__global__ void __launch_bounds__(256) gemm_mma(
    const float* __restrict__ bias, float* __restrict__ Cout)
{
    extern __shared__ __align__(16) char smem[];
    const uint32_t sb = smem_u32(smem);

    const int tid  = threadIdx.x;
    const int wid  = tid >> 5, lane = tid & 31;
    const int wm   = wid >> 2, wn = wid & 3;          // 2 x 4 warp grid
    const int row0 = (int)blockIdx.y << 7, col0 = (int)blockIdx.x << 7;

    // ---- loaders: thread -> (row, 16-elem half) of the 128x32 tile ----
    const int lr = tid >> 1, lh = tid & 1;
    const __nv_bfloat16* pa = g_ihi + (size_t)(row0 + lr) * DIM + lh*16;
    const __nv_bfloat16* pl = g_ilo + (size_t)(row0 + lr) * DIM + lh*16;
    const __nv_bfloat16* pw = g_whi + (size_t)(col0 + lr) * DIM + lh*16;
    const __nv_bfloat16* pm = g_wlo + (size_t)(col0 + lr) * DIM + lh*16;
    const uint32_t sdst = sb + lr*(ROWPAD*2) + lh*32;

    auto load_stage = [&](int ci, int st) {
        uint32_t d = sdst + st*STAGE_B;
        int ko = ci * BK;
        cp16(d,                    pa + ko);  cp16(d + 16,             pa + ko + 8);
        cp16(d + OPBUF_B,          pl + ko);  cp16(d + OPBUF_B + 16,   pl + ko + 8);
        cp16(d + 2*OPBUF_B,        pw + ko);  cp16(d + 2*OPBUF_B + 16, pw + ko + 8);
        cp16(d + 3*OPBUF_B,        pm + ko);  cp16(d + 3*OPBUF_B + 16, pm + ko + 8);
    };

    float c[4][4][4];
    #pragma unroll
    for (int mi = 0; mi < 4; mi++)
        #pragma unroll
        for (int ni = 0; ni < 4; ni++)
            #pragma unroll
            for (int j = 0; j < 4; j++) c[mi][ni][j] = 0.f;

    const int lr4 = lane >> 2;        // 0..7
    const int lk2 = (lane & 3) * 2;   // 0,2,4,6

    load_stage(0, 0);
    CP_COMMIT();

    const int NCHUNK = DIM / BK;   // 32
    for (int ci = 0; ci < NCHUNK; ci++) {
        if (ci + 1 < NCHUNK) { load_stage(ci + 1, (ci + 1) & 1); CP_COMMIT(); CP_WAIT(1); }
        else                 { CP_WAIT(0); }
        __syncthreads();

        const uint32_t sA   = sb + (ci & 1)*STAGE_B;
        const uint32_t sAlo = sA + OPBUF_B;
        const uint32_t sW   = sA + 2*OPBUF_B;
        const uint32_t sWlo = sA + 3*OPBUF_B;

        #pragma unroll
        for (int kk = 0; kk < 2; kk++) {
            const int c0 = kk*16 + lk2;           // k column (bf16 elems)
            uint32_t bh0[4], bh1[4], bl0[4], bl1[4];
            #pragma unroll
            for (int ni = 0; ni < 4; ni++) {
                const uint32_t wr = (uint32_t)(wn*32 + ni*8 + lr4) * (ROWPAD*2);
                bh0[ni] = lds32(sW   + wr + c0*2);
                bh1[ni] = lds32(sW   + wr + (c0+8)*2);
                bl0[ni] = lds32(sWlo + wr + c0*2);
                bl1[ni] = lds32(sWlo + wr + (c0+8)*2);
            }
            #pragma unroll
            for (int mi = 0; mi < 4; mi++) {
                const uint32_t ar0 = (uint32_t)(wm*64 + mi*16 + lr4) * (ROWPAD*2);
                const uint32_t ar8 = ar0 + 8*(ROWPAD*2);
                uint32_t ah[4], al[4];
                ah[0] = lds32(sA + ar0 + c0*2);
                ah[1] = lds32(sA + ar8 + c0*2);
                ah[2] = lds32(sA + ar0 + (c0+8)*2);
                ah[3] = lds32(sA + ar8 + (c0+8)*2);
                al[0] = lds32(sAlo + ar0 + c0*2);
                al[1] = lds32(sAlo + ar8 + c0*2);
                al[2] = lds32(sAlo + ar0 + (c0+8)*2);
                al[3] = lds32(sAlo + ar8 + (c0+8)*2);
                #pragma unroll
                for (int ni = 0; ni < 4; ni++) {
                    mma16816(c[mi][ni], ah, bh0[ni], bh1[ni]);
                    mma16816(c[mi][ni], ah, bl0[ni], bl1[ni]);
                    mma16816(c[mi][ni], al, bh0[ni], bh1[ni]);
                }
            }
        }
        __syncthreads();
    }

    // ---- epilogue from fragments ----
    const int r_l = lane >> 2;
    const int c_l = (lane & 3)*2;
    #pragma unroll
    for (int mi = 0; mi < 4; mi++) {
        #pragma unroll
        for (int ni = 0; ni < 4; ni++) {
            const int n = col0 + wn*32 + ni*8 + c_l;
            float2 bv = *(const float2*)&bias[n];
            #pragma unroll
            for (int hf = 0; hf < 2; hf++) {
                const int m = row0 + wm*64 + mi*16 + r_l + hf*8;
                float e = c[mi][ni][2*hf]   + bv.x;
                float o = c[mi][ni][2*hf+1] + bv.y;
                if (MODE == 3) {
                    *(float2*)&Cout[(size_t)m*DIM + n] = make_float2(e, o);
                } else {
                    float* dst = (MODE == 0) ? g_q : (MODE == 1) ? g_k : g_v;
                    const int b = m >> 11, sIdx = m & (SEQ - 1);
                    const int h = n >> 6, d0 = n & 63;
                    float re, im;
                    if (MODE <= 1) {
                        float cc = g_cos[sIdx*32 + (d0 >> 1)];
                        float ss = g_sin[sIdx*32 + (d0 >> 1)];
                        re = e*cc - o*ss;
                        im = e*ss + o*cc;
                    } else { re = e; im = o; }
                    *(float2*)&dst[(size_t)((b*NH + h)*SEQ + sIdx)*HD + d0] = make_float2(re, im);
                }
            }
        }
    }
}

// ---------------------------------------------------------------------------
// Flash attention (fp32 SIMT, FFMA2) — R3-proven. Epilogue writes hi/lo bf16
// splits directly into the O-projection's A buffers (device globals).
// ---------------------------------------------------------------------------
__global__ void __launch_bounds__(256) attn_kernel() {
    __shared__ __align__(16) float Qs[64*64];   // [d][q]
    __shared__ __align__(16) float KP[64*64];   // K^T [d][kv] -> P [q][kv]
    __shared__ __align__(16) float Vs[64*64];   // [kv][d]

    const int tid = threadIdx.x;
    const int tx = tid & 15, ty = tid >> 4;
    const int lr = tid >> 2, lc = (tid & 3) << 2;
    const int qt = blockIdx.x, bh = blockIdx.y;

    const float* Qg = g_q + (bh*SEQ + qt*64)*HD;
    const float* Kg = g_k + bh*SEQ*HD;
    const float* Vg = g_v + bh*SEQ*HD;

    {   // Q tile transposed + pre-scaled
        const float sc = 0.125f;
        #pragma unroll
        for (int j = 0; j < 4; j++) {
            int c = lc + 16*j;
            float4 q4 = *(const float4*)(Qg + lr*HD + c);
            Qs[(c+0)*64 + lr] = q4.x*sc; Qs[(c+1)*64 + lr] = q4.y*sc;
            Qs[(c+2)*64 + lr] = q4.z*sc; Qs[(c+3)*64 + lr] = q4.w*sc;
        }
    }

    float m_i[4] = {-1e30f, -1e30f, -1e30f, -1e30f};
    float l_i[4] = {};
    float2 o01[4] = {}, o23[4] = {};

    for (int kt = 0; kt < SEQ; kt += 64) {
        #pragma unroll
        for (int j = 0; j < 4; j++) {
            int c = lc + 16*j;
            float4 k4 = *(const float4*)(Kg + (kt + lr)*HD + c);
            KP[(c+0)*64 + lr] = k4.x; KP[(c+1)*64 + lr] = k4.y;
            KP[(c+2)*64 + lr] = k4.z; KP[(c+3)*64 + lr] = k4.w;
            *(float4*)&Vs[lr*64 + c] = *(const float4*)(Vg + (kt + lr)*HD + c);
        }
        __syncthreads();

        float2 s01[4] = {}, s23[4] = {};
        #pragma unroll 4
        for (int d = 0; d < 64; d++) {
            float4 a4  = *(const float4*)&Qs[d*64 + 4*ty];
            float2 b01 = *(const float2*)&KP[d*64 + 2*tx];
            float2 b23 = *(const float2*)&KP[d*64 + 2*tx + 32];
            float ar[4] = {a4.x, a4.y, a4.z, a4.w};
            #pragma unroll
            for (int r = 0; r < 4; r++) {
                float2 a2 = make_float2(ar[r], ar[r]);
                f2fma(s01[r], a2, b01);
                f2fma(s23[r], a2, b23);
            }
        }
        __syncthreads();

        #pragma unroll
        for (int r = 0; r < 4; r++) {
            float mx = fmaxf(fmaxf(s01[r].x, s01[r].y), fmaxf(s23[r].x, s23[r].y));
            #pragma unroll
            for (int off = 8; off; off >>= 1)
                mx = fmaxf(mx, __shfl_xor_sync(0xffffffffu, mx, off));
            float mn = fmaxf(m_i[r], mx);
            float p00 = __expf(s01[r].x - mn), p01 = __expf(s01[r].y - mn);
            float p10 = __expf(s23[r].x - mn), p11 = __expf(s23[r].y - mn);
            float ls = p00 + p01 + p10 + p11;
            #pragma unroll
            for (int off = 8; off; off >>= 1)
                ls += __shfl_xor_sync(0xffffffffu, ls, off);
            float alpha = __expf(m_i[r] - mn);
            m_i[r] = mn;
            l_i[r] = l_i[r]*alpha + ls;
            float2 al2 = make_float2(alpha, alpha);
            f2mul(o01[r], al2);
            f2mul(o23[r], al2);
            int rg = 4*ty + r;
            *(float2*)&KP[rg*64 + 2*tx]      = make_float2(p00, p01);
            *(float2*)&KP[rg*64 + 2*tx + 32] = make_float2(p10, p11);
        }
        __syncthreads();

        #pragma unroll 4
        for (int k = 0; k < 64; k++) {
            float2 b01 = *(const float2*)&Vs[k*64 + 2*tx];
            float2 b23 = *(const float2*)&Vs[k*64 + 2*tx + 32];
            float pr[4] = { KP[(4*ty+0)*64 + k], KP[(4*ty+1)*64 + k],
                            KP[(4*ty+2)*64 + k], KP[(4*ty+3)*64 + k] };
            #pragma unroll
            for (int r = 0; r < 4; r++) {
                float2 a2 = make_float2(pr[r], pr[r]);
                f2fma(o01[r], a2, b01);
                f2fma(o23[r], a2, b23);
            }
        }
        __syncthreads();
    }

    // write [B,S,H,hd] as bf16 hi/lo splits -> O-proj GEMM A operand
    const int b = bh >> 4, h = bh & 15;
    #pragma unroll
    for (int r = 0; r < 4; r++) {
        float inv = 1.0f / l_i[r];
        int srow = qt*64 + 4*ty + r;
        int base = ((b*SEQ + srow)*NH + h)*HD;
        float v0 = o01[r].x*inv, v1 = o01[r].y*inv;
        float v2 = o23[r].x*inv, v3 = o23[r].y*inv;
        __nv_bfloat16 h0 = __float2bfloat16(v0), h1 = __float2bfloat16(v1);
        __nv_bfloat16 h2 = __float2bfloat16(v2), h3 = __float2bfloat16(v3);
        __nv_bfloat162 H01, H23, L01, L23;
        H01.x = h0; H01.y = h1; H23.x = h2; H23.y = h3;
        L01.x = __float2bfloat16(v0 - __bfloat162float(h0));
        L01.y = __float2bfloat16(v1 - __bfloat162float(h1));
        L23.x = __float2bfloat16(v2 - __bfloat162float(h2));
        L23.y = __float2bfloat16(v3 - __bfloat162float(h3));
        *(__nv_bfloat162*)&g_ihi[base + 2*tx]      = H01;
        *(__nv_bfloat162*)&g_ihi[base + 2*tx + 32] = H23;
        *(__nv_bfloat162*)&g_ilo[base + 2*tx]      = L01;
        *(__nv_bfloat162*)&g_ilo[base + 2*tx + 32] = L23;
    }
}

// ---------------------------------------------------------------------------
extern "C" void kernel_launch(void* const* d_in, const int* in_sizes, int n_in,
                              void* d_out, int out_size)
{
    const float* q  = (const float*)d_in[0];
    const float* k  = (const float*)d_in[1];
    const float* v  = (const float*)d_in[2];
    const float* qw = (const float*)d_in[3];
    const float* qb = (const float*)d_in[4];
    const float* kw = (const float*)d_in[5];
    const float* kb = (const float*)d_in[6];
    const float* vw = (const float*)d_in[7];
    const float* vb = (const float*)d_in[8];
    const float* ow = (const float*)d_in[9];
    const float* ob = (const float*)d_in[10];
    float* out = (float*)d_out;

    cudaFuncSetAttribute(gemm_mma<0>, cudaFuncAttributeMaxDynamicSharedMemorySize, SMEM_B);
    cudaFuncSetAttribute(gemm_mma<1>, cudaFuncAttributeMaxDynamicSharedMemorySize, SMEM_B);
    cudaFuncSetAttribute(gemm_mma<2>, cudaFuncAttributeMaxDynamicSharedMemorySize, SMEM_B);
    cudaFuncSetAttribute(gemm_mma<3>, cudaFuncAttributeMaxDynamicSharedMemorySize, SMEM_B);

    rope_table_kernel<<<64, 1024>>>();

    const int N4_IN = MROWS*DIM/4;   // 1048576
    const int N4_W  = DIM*DIM/4;     // 262144
    dim3 gg(DIM/128, MROWS/128);     // (8, 32)

    cvt_split<0><<<N4_IN/256, 256>>>(q, N4_IN);
    cvt_split<1><<<N4_W/256, 256>>>(qw, N4_W);
    gemm_mma<0><<<gg, 256, SMEM_B>>>(qb, nullptr);

    cvt_split<0><<<N4_IN/256, 256>>>(k, N4_IN);
    cvt_split<1><<<N4_W/256, 256>>>(kw, N4_W);
    gemm_mma<1><<<gg, 256, SMEM_B>>>(kb, nullptr);

    cvt_split<0><<<N4_IN/256, 256>>>(v, N4_IN);
    cvt_split<1><<<N4_W/256, 256>>>(vw, N4_W);
    gemm_mma<2><<<gg, 256, SMEM_B>>>(vb, nullptr);

    attn_kernel<<<dim3(SEQ/64, NB*NH), 256>>>();   // writes g_ihi/g_ilo

    cvt_split<1><<<N4_W/256, 256>>>(ow, N4_W);
    gemm_mma<3><<<gg, 256, SMEM_B>>>(ob, out);
}

// round 8
// speedup vs baseline: 1.6781x; 1.6781x over previous
#include <cuda_runtime.h>
#include <cuda_bf16.h>
#include <cstdint>

#define NB   2
#define SEQ  2048
#define DIM  1024
#define NH   16
#define HD   64
#define MROWS (NB*SEQ)   // 4096

// ---------------------------------------------------------------------------
// Scratch (allocation-free rule: __device__ globals; device-code refs ONLY)
// ---------------------------------------------------------------------------
__device__ float g_q[NB*NH*HD*SEQ];     // Q roped+scaled, TRANSPOSED [B,H,hd,S]
__device__ float g_k[NB*NH*HD*SEQ];     // K roped,        TRANSPOSED [B,H,hd,S]
__device__ float g_v[NB*NH*SEQ*HD];     // V               [B,H,S,hd]
// bf16 hi/lo split operand buffers (per-tensor so kernels can merge)
__device__ __nv_bfloat16 g_aq_h[MROWS*DIM], g_aq_l[MROWS*DIM];
__device__ __nv_bfloat16 g_ak_h[MROWS*DIM], g_ak_l[MROWS*DIM];
__device__ __nv_bfloat16 g_av_h[MROWS*DIM], g_av_l[MROWS*DIM];
__device__ __nv_bfloat16 g_ao_h[MROWS*DIM], g_ao_l[MROWS*DIM];  // attn out
__device__ __nv_bfloat16 g_wq_h[DIM*DIM], g_wq_l[DIM*DIM];
__device__ __nv_bfloat16 g_wk_h[DIM*DIM], g_wk_l[DIM*DIM];
__device__ __nv_bfloat16 g_wv_h[DIM*DIM], g_wv_l[DIM*DIM];
__device__ __nv_bfloat16 g_wo_h[DIM*DIM], g_wo_l[DIM*DIM];
__device__ float g_cos[SEQ*(HD/2)];
__device__ float g_sin[SEQ*(HD/2)];

// ---------------------------------------------------------------------------
// Baseline-PTX helpers (compute_103-safe)
// ---------------------------------------------------------------------------
__device__ __forceinline__ uint32_t smem_u32(const void* p) {
    uint32_t a;
    asm("{ .reg .u64 t; cvta.to.shared.u64 t, %1; cvt.u32.u64 %0, t; }" : "=r"(a) : "l"(p));
    return a;
}
__device__ __forceinline__ void cp16(uint32_t dst, const void* src) {
    asm volatile("cp.async.cg.shared.global [%0], [%1], 16;"
                 :: "r"(dst), "l"(__cvta_generic_to_global(src)) : "memory");
}
#define CP_COMMIT() asm volatile("cp.async.commit_group;" ::: "memory")
#define CP_WAIT(n)  asm volatile("cp.async.wait_group %0;" :: "n"(n) : "memory")

__device__ __forceinline__ uint32_t lds32(uint32_t a) {
    uint32_t v;
    asm volatile("ld.shared.b32 %0, [%1];" : "=r"(v) : "r"(a));
    return v;
}
__device__ __forceinline__ void mma16816(float* c, const uint32_t* a, uint32_t b0, uint32_t b1) {
    asm volatile("mma.sync.aligned.m16n8k16.row.col.f32.bf16.bf16.f32 "
                 "{%0,%1,%2,%3}, {%4,%5,%6,%7}, {%8,%9}, {%0,%1,%2,%3};"
                 : "+f"(c[0]), "+f"(c[1]), "+f"(c[2]), "+f"(c[3])
                 : "r"(a[0]), "r"(a[1]), "r"(a[2]), "r"(a[3]), "r"(b0), "r"(b1));
}
__device__ __forceinline__ void f2fma(float2& c, float2 a, float2 b) {
    unsigned long long cc = *reinterpret_cast<unsigned long long*>(&c);
    unsigned long long aa = *reinterpret_cast<unsigned long long*>(&a);
    unsigned long long bb = *reinterpret_cast<unsigned long long*>(&b);
    asm("fma.rn.f32x2 %0, %1, %2, %0;" : "+l"(cc) : "l"(aa), "l"(bb));
    c = *reinterpret_cast<float2*>(&cc);
}
__device__ __forceinline__ void f2mul(float2& c, float2 a) {
    unsigned long long cc = *reinterpret_cast<unsigned long long*>(&c);
    unsigned long long aa = *reinterpret_cast<unsigned long long*>(&a);
    asm("mul.rn.f32x2 %0, %0, %1;" : "+l"(cc) : "l"(aa));
    c = *reinterpret_cast<float2*>(&cc);
}

// ---------------------------------------------------------------------------
// RoPE table — 32 DP pows per block (smem-shared), fp32 angle (matches the
// reference's f32 product), double range-reduction, fp32 sincos.
// ---------------------------------------------------------------------------
__global__ void rope_table_kernel() {
    __shared__ float invs[32];
    int tid = threadIdx.x;
    if (tid < 32)
        invs[tid] = (float)pow(10000.0, -(double)tid / 32.0);
    __syncthreads();
    int i = blockIdx.x * blockDim.x + tid;
    int s = i >> 5;
    int p = i & 31;
    float ang = (float)s * invs[p];          // same f32 value as reference
    double ad = (double)ang;
    double k  = (double)__double2int_rn(ad * 0.15915494309189535);
    float r   = (float)(ad - k * 6.283185307179586);
    g_cos[i] = cosf(r);
    g_sin[i] = sinf(r);
}

// ---------------------------------------------------------------------------
// fp32 -> (hi, lo) bf16 splits. cvt_in: z in {0,1,2} = q,k,v inputs.
// cvt_w: z in {0..3} = qw,kw,vw,ow.
// ---------------------------------------------------------------------------
__device__ __forceinline__ void split4(float4 v, __nv_bfloat16* hi, __nv_bfloat16* lo, int i) {
    __nv_bfloat16 h0 = __float2bfloat16(v.x), h1 = __float2bfloat16(v.y);
    __nv_bfloat16 h2 = __float2bfloat16(v.z), h3 = __float2bfloat16(v.w);
    __nv_bfloat162 H01, H23, L01, L23;
    H01.x = h0; H01.y = h1; H23.x = h2; H23.y = h3;
    L01.x = __float2bfloat16(v.x - __bfloat162float(h0));
    L01.y = __float2bfloat16(v.y - __bfloat162float(h1));
    L23.x = __float2bfloat16(v.z - __bfloat162float(h2));
    L23.y = __float2bfloat16(v.w - __bfloat162float(h3));
    ((__nv_bfloat162*)hi)[2*i]   = H01;
    ((__nv_bfloat162*)hi)[2*i+1] = H23;
    ((__nv_bfloat162*)lo)[2*i]   = L01;
    ((__nv_bfloat162*)lo)[2*i+1] = L23;
}
__global__ void cvt_in(const float* __restrict__ q, const float* __restrict__ k,
                       const float* __restrict__ v) {
    int z = blockIdx.z;
    int i = blockIdx.x * blockDim.x + threadIdx.x;
    const float* src = (z == 0) ? q : (z == 1) ? k : v;
    __nv_bfloat16* hi = (z == 0) ? g_aq_h : (z == 1) ? g_ak_h : g_av_h;
    __nv_bfloat16* lo = (z == 0) ? g_aq_l : (z == 1) ? g_ak_l : g_av_l;
    split4(((const float4*)src)[i], hi, lo, i);
}
__global__ void cvt_w(const float* __restrict__ qw, const float* __restrict__ kw,
                      const float* __restrict__ vw, const float* __restrict__ ow) {
    int z = blockIdx.z;
    int i = blockIdx.x * blockDim.x + threadIdx.x;
    const float* src = (z == 0) ? qw : (z == 1) ? kw : (z == 2) ? vw : ow;
    __nv_bfloat16* hi = (z == 0) ? g_wq_h : (z == 1) ? g_wk_h : (z == 2) ? g_wv_h : g_wo_h;
    __nv_bfloat16* lo = (z == 0) ? g_wq_l : (z == 1) ? g_wk_l : (z == 2) ? g_wv_l : g_wo_l;
    split4(((const float4*)src)[i], hi, lo, i);
}

// ---------------------------------------------------------------------------
// mma.sync NT GEMM body (proven R7): CTA 128x128, 8 warps, BK=32, 2-stage
// cp.async, explicit per-lane fragment loads, 3-term bf16 split.
// ---------------------------------------------------------------------------
#define BK        32
#define ROWPAD    40
#define OPBUF_B   (128*ROWPAD*2)
#define STAGE_B   (4*OPBUF_B)
#define SMEM_B    (2*STAGE_B)

// GEMM core: computes the 128x128 tile into c[][][] given operand pointers.
__device__ __forceinline__ void gemm_core(
    const __nv_bfloat16* Ah, const __nv_bfloat16* Al,
    const __nv_bfloat16* Wh, const __nv_bfloat16* Wl,
    int row0, int col0, char* smem, uint32_t sb, float c[4][4][4])
{
    const int tid  = threadIdx.x;
    const int lane = tid & 31;
    const int wid  = tid >> 5;
    const int wm   = wid >> 2, wn = wid & 3;

    const int lr = tid >> 1, lh = tid & 1;
    const __nv_bfloat16* pa = Ah + (size_t)(row0 + lr) * DIM + lh*16;
    const __nv_bfloat16* pl = Al + (size_t)(row0 + lr) * DIM + lh*16;
    const __nv_bfloat16* pw = Wh + (size_t)(col0 + lr) * DIM + lh*16;
    const __nv_bfloat16* pm = Wl + (size_t)(col0 + lr) * DIM + lh*16;
    const uint32_t sdst = sb + lr*(ROWPAD*2) + lh*32;

    auto load_stage = [&](int ci, int st) {
        uint32_t d = sdst + st*STAGE_B;
        int ko = ci * BK;
        cp16(d,                    pa + ko);  cp16(d + 16,             pa + ko + 8);
        cp16(d + OPBUF_B,          pl + ko);  cp16(d + OPBUF_B + 16,   pl + ko + 8);
        cp16(d + 2*OPBUF_B,        pw + ko);  cp16(d + 2*OPBUF_B + 16, pw + ko + 8);
        cp16(d + 3*OPBUF_B,        pm + ko);  cp16(d + 3*OPBUF_B + 16, pm + ko + 8);
    };

    const int lr4 = lane >> 2;
    const int lk2 = (lane & 3) * 2;

    load_stage(0, 0);
    CP_COMMIT();

    const int NCHUNK = DIM / BK;
    for (int ci = 0; ci < NCHUNK; ci++) {
        if (ci + 1 < NCHUNK) { load_stage(ci + 1, (ci + 1) & 1); CP_COMMIT(); CP_WAIT(1); }
        else                 { CP_WAIT(0); }
        __syncthreads();

        const uint32_t sA   = sb + (ci & 1)*STAGE_B;
        const uint32_t sAlo = sA + OPBUF_B;
        const uint32_t sW   = sA + 2*OPBUF_B;
        const uint32_t sWlo = sA + 3*OPBUF_B;

        #pragma unroll
        for (int kk = 0; kk < 2; kk++) {
            const int c0 = kk*16 + lk2;
            uint32_t bh0[4], bh1[4], bl0[4], bl1[4];
            #pragma unroll
            for (int ni = 0; ni < 4; ni++) {
                const uint32_t wr = (uint32_t)(wn*32 + ni*8 + lr4) * (ROWPAD*2);
                bh0[ni] = lds32(sW   + wr + c0*2);
                bh1[ni] = lds32(sW   + wr + (c0+8)*2);
                bl0[ni] = lds32(sWlo + wr + c0*2);
                bl1[ni] = lds32(sWlo + wr + (c0+8)*2);
            }
            #pragma unroll
            for (int mi = 0; mi < 4; mi++) {
                const uint32_t ar0 = (uint32_t)(wm*64 + mi*16 + lr4) * (ROWPAD*2);
                const uint32_t ar8 = ar0 + 8*(ROWPAD*2);
                uint32_t ah[4], al[4];
                ah[0] = lds32(sA + ar0 + c0*2);
                ah[1] = lds32(sA + ar8 + c0*2);
                ah[2] = lds32(sA + ar0 + (c0+8)*2);
                ah[3] = lds32(sA + ar8 + (c0+8)*2);
                al[0] = lds32(sAlo + ar0 + c0*2);
                al[1] = lds32(sAlo + ar8 + c0*2);
                al[2] = lds32(sAlo + ar0 + (c0+8)*2);
                al[3] = lds32(sAlo + ar8 + (c0+8)*2);
                #pragma unroll
                for (int ni = 0; ni < 4; ni++) {
                    mma16816(c[mi][ni], ah, bh0[ni], bh1[ni]);
                    mma16816(c[mi][ni], ah, bl0[ni], bl1[ni]);
                    mma16816(c[mi][ni], al, bh0[ni], bh1[ni]);
                }
            }
        }
        __syncthreads();
    }
}

// Fused Q/K/V projection GEMM: z = blockIdx.z selects operands + epilogue.
// Q/K: +RoPE (Q pre-scaled by 0.125), scatter TRANSPOSED [B,H,hd,S].
// V: scatter [B,H,S,hd].
__global__ void __launch_bounds__(256) gemm_qkv(
    const float* __restrict__ qb, const float* __restrict__ kb,
    const float* __restrict__ vb)
{
    extern __shared__ __align__(16) char smem[];
    const uint32_t sb = smem_u32(smem);
    const int z = blockIdx.z;
    const int row0 = (int)blockIdx.y << 7, col0 = (int)blockIdx.x << 7;

    const __nv_bfloat16* Ah = (z == 0) ? g_aq_h : (z == 1) ? g_ak_h : g_av_h;
    const __nv_bfloat16* Al = (z == 0) ? g_aq_l : (z == 1) ? g_ak_l : g_av_l;
    const __nv_bfloat16* Wh = (z == 0) ? g_wq_h : (z == 1) ? g_wk_h : g_wv_h;
    const __nv_bfloat16* Wl = (z == 0) ? g_wq_l : (z == 1) ? g_wk_l : g_wv_l;
    const float* bias = (z == 0) ? qb : (z == 1) ? kb : vb;

    float c[4][4][4];
    #pragma unroll
    for (int mi = 0; mi < 4; mi++)
        #pragma unroll
        for (int ni = 0; ni < 4; ni++)
            #pragma unroll
            for (int j = 0; j < 4; j++) c[mi][ni][j] = 0.f;

    gemm_core(Ah, Al, Wh, Wl, row0, col0, smem, sb, c);

    const int lane = threadIdx.x & 31, wid = threadIdx.x >> 5;
    const int wm = wid >> 2, wn = wid & 3;
    const int r_l = lane >> 2, c_l = (lane & 3)*2;
    float* dst = (z == 0) ? g_q : (z == 1) ? g_k : g_v;
    #pragma unroll
    for (int mi = 0; mi < 4; mi++) {
        #pragma unroll
        for (int ni = 0; ni < 4; ni++) {
            const int n = col0 + wn*32 + ni*8 + c_l;
            float2 bv = *(const float2*)&bias[n];
            const int h = n >> 6, d0 = n & 63;
            #pragma unroll
            for (int hf = 0; hf < 2; hf++) {
                const int m = row0 + wm*64 + mi*16 + r_l + hf*8;
                const int b = m >> 11, sIdx = m & (SEQ - 1);
                float e = c[mi][ni][2*hf]   + bv.x;
                float o = c[mi][ni][2*hf+1] + bv.y;
                if (z <= 1) {
                    if (z == 0) { e *= 0.125f; o *= 0.125f; }   // pre-scale Q
                    float cc = g_cos[sIdx*32 + (d0 >> 1)];
                    float ss = g_sin[sIdx*32 + (d0 >> 1)];
                    float re = e*cc - o*ss;
                    float im = e*ss + o*cc;
                    size_t ti = ((size_t)(b*NH + h)*HD + d0)*SEQ + sIdx;  // transposed
                    dst[ti]       = re;
                    dst[ti + SEQ] = im;
                } else {
                    *(float2*)&dst[(size_t)((b*NH + h)*SEQ + sIdx)*HD + d0] = make_float2(e, o);
                }
            }
        }
    }
}

// Output projection GEMM: A = g_ao pair, W = g_wo pair -> Cout fp32.
__global__ void __launch_bounds__(256) gemm_o(
    const float* __restrict__ bias, float* __restrict__ Cout)
{
    extern __shared__ __align__(16) char smem[];
    const uint32_t sb = smem_u32(smem);
    const int row0 = (int)blockIdx.y << 7, col0 = (int)blockIdx.x << 7;

    float c[4][4][4];
    #pragma unroll
    for (int mi = 0; mi < 4; mi++)
        #pragma unroll
        for (int ni = 0; ni < 4; ni++)
            #pragma unroll
            for (int j = 0; j < 4; j++) c[mi][ni][j] = 0.f;

    gemm_core(g_ao_h, g_ao_l, g_wo_h, g_wo_l, row0, col0, smem, sb, c);

    const int lane = threadIdx.x & 31, wid = threadIdx.x >> 5;
    const int wm = wid >> 2, wn = wid & 3;
    const int r_l = lane >> 2, c_l = (lane & 3)*2;
    #pragma unroll
    for (int mi = 0; mi < 4; mi++) {
        #pragma unroll
        for (int ni = 0; ni < 4; ni++) {
            const int n = col0 + wn*32 + ni*8 + c_l;
            float2 bv = *(const float2*)&bias[n];
            #pragma unroll
            for (int hf = 0; hf < 2; hf++) {
                const int m = row0 + wm*64 + mi*16 + r_l + hf*8;
                *(float2*)&Cout[(size_t)m*DIM + n] =
                    make_float2(c[mi][ni][2*hf] + bv.x, c[mi][ni][2*hf+1] + bv.y);
            }
        }
    }
}

// ---------------------------------------------------------------------------
// Flash attention (fp32 FFMA2) — pipelined: Q/K pre-transposed [d][s] in gmem,
// all tiles via cp.async; K/V double-buffered (prefetch during compute);
// separate P buffer (2 syncs/tile). 96KB dynamic smem.
// Layout: Qs[d][q] @0, Ps[q][kv] @4096, Kt[2][d][kv] @8192, Vs[2][kv][d] @16384 (floats).
// ---------------------------------------------------------------------------
#define ATT_SMEM 98304
__global__ void __launch_bounds__(256) attn_kernel() {
    extern __shared__ __align__(16) float As[];
    float* Qs = As;
    float* Ps = As + 4096;
    const uint32_t sbase = smem_u32(As);

    const int tid = threadIdx.x;
    const int tx = tid & 15, ty = tid >> 4;
    const int qt = blockIdx.x, bh = blockIdx.y;

    const float* Qg = g_q + (size_t)bh*HD*SEQ + qt*64;   // [d][s] rows
    const float* Kg = g_k + (size_t)bh*HD*SEQ;
    const float* Vg = g_v + (size_t)bh*SEQ*HD;

    // Q tile: 64 rows(d) x 256B; 1024 chunks of 16B, 4 per thread
    #pragma unroll
    for (int j = 0; j < 4; j++) {
        int cid = tid*4 + j, row = cid >> 4, c4 = (cid & 15)*4;
        cp16(sbase + (uint32_t)(row*64 + c4)*4, Qg + (size_t)row*SEQ + c4);
    }
    auto loadKV = [&](int it, int buf) {
        int kt0 = it * 64;
        #pragma unroll
        for (int j = 0; j < 4; j++) {
            int cid = tid*4 + j, row = cid >> 4, c4 = (cid & 15)*4;
            cp16(sbase + (uint32_t)(8192 + buf*4096 + row*64 + c4)*4,
                 Kg + (size_t)row*SEQ + kt0 + c4);
            cp16(sbase + (uint32_t)(16384 + buf*4096 + row*64 + c4)*4,
                 Vg + (size_t)(kt0 + row)*HD + c4);
        }
    };
    loadKV(0, 0);
    CP_COMMIT();

    float m_i[4] = {-1e30f, -1e30f, -1e30f, -1e30f};
    float l_i[4] = {};
    float2 o01[4] = {}, o23[4] = {};

    for (int it = 0; it < 32; it++) {
        CP_WAIT(0);
        __syncthreads();
        if (it + 1 < 32) { loadKV(it + 1, (it + 1) & 1); CP_COMMIT(); }

        const float* K_ = As + 8192  + (it & 1)*4096;   // [d][kv]
        const float* V_ = As + 16384 + (it & 1)*4096;   // [kv][d]

        // S = Q K^T (Q pre-scaled + roped)
        float2 s01[4] = {}, s23[4] = {};
        #pragma unroll 4
        for (int d = 0; d < 64; d++) {
            float4 a4  = *(const float4*)&Qs[d*64 + 4*ty];
            float2 b01 = *(const float2*)&K_[d*64 + 2*tx];
            float2 b23 = *(const float2*)&K_[d*64 + 2*tx + 32];
            float ar[4] = {a4.x, a4.y, a4.z, a4.w};
            #pragma unroll
            for (int r = 0; r < 4; r++) {
                float2 a2 = make_float2(ar[r], ar[r]);
                f2fma(s01[r], a2, b01);
                f2fma(s23[r], a2, b23);
            }
        }

        // online softmax; write P to its own buffer (no pre-sync needed)
        #pragma unroll
        for (int r = 0; r < 4; r++) {
            float mx = fmaxf(fmaxf(s01[r].x, s01[r].y), fmaxf(s23[r].x, s23[r].y));
            #pragma unroll
            for (int off = 8; off; off >>= 1)
                mx = fmaxf(mx, __shfl_xor_sync(0xffffffffu, mx, off));
            float mn = fmaxf(m_i[r], mx);
            float p00 = __expf(s01[r].x - mn), p01 = __expf(s01[r].y - mn);
            float p10 = __expf(s23[r].x - mn), p11 = __expf(s23[r].y - mn);
            float ls = p00 + p01 + p10 + p11;
            #pragma unroll
            for (int off = 8; off; off >>= 1)
                ls += __shfl_xor_sync(0xffffffffu, ls, off);
            float alpha = __expf(m_i[r] - mn);
            m_i[r] = mn;
            l_i[r] = l_i[r]*alpha + ls;
            float2 al2 = make_float2(alpha, alpha);
            f2mul(o01[r], al2);
            f2mul(o23[r], al2);
            int rg = 4*ty + r;
            *(float2*)&Ps[rg*64 + 2*tx]      = make_float2(p00, p01);
            *(float2*)&Ps[rg*64 + 2*tx + 32] = make_float2(p10, p11);
        }
        __syncthreads();

        // O += P V
        #pragma unroll 4
        for (int k = 0; k < 64; k++) {
            float2 b01 = *(const float2*)&V_[k*64 + 2*tx];
            float2 b23 = *(const float2*)&V_[k*64 + 2*tx + 32];
            float pr[4] = { Ps[(4*ty+0)*64 + k], Ps[(4*ty+1)*64 + k],
                            Ps[(4*ty+2)*64 + k], Ps[(4*ty+3)*64 + k] };
            #pragma unroll
            for (int r = 0; r < 4; r++) {
                float2 a2 = make_float2(pr[r], pr[r]);
                f2fma(o01[r], a2, b01);
                f2fma(o23[r], a2, b23);
            }
        }
        // no sync here: next iter's CP_WAIT + sync protects buffer reuse
    }

    // write [B,S,H,hd] bf16 hi/lo splits -> O-proj A operand
    const int b = bh >> 4, h = bh & 15;
    #pragma unroll
    for (int r = 0; r < 4; r++) {
        float inv = 1.0f / l_i[r];
        int srow = qt*64 + 4*ty + r;
        int base = ((b*SEQ + srow)*NH + h)*HD;
        float v0 = o01[r].x*inv, v1 = o01[r].y*inv;
        float v2 = o23[r].x*inv, v3 = o23[r].y*inv;
        __nv_bfloat16 h0 = __float2bfloat16(v0), h1 = __float2bfloat16(v1);
        __nv_bfloat16 h2 = __float2bfloat16(v2), h3 = __float2bfloat16(v3);
        __nv_bfloat162 H01, H23, L01, L23;
        H01.x = h0; H01.y = h1; H23.x = h2; H23.y = h3;
        L01.x = __float2bfloat16(v0 - __bfloat162float(h0));
        L01.y = __float2bfloat16(v1 - __bfloat162float(h1));
        L23.x = __float2bfloat16(v2 - __bfloat162float(h2));
        L23.y = __float2bfloat16(v3 - __bfloat162float(h3));
        *(__nv_bfloat162*)&g_ao_h[base + 2*tx]      = H01;
        *(__nv_bfloat162*)&g_ao_h[base + 2*tx + 32] = H23;
        *(__nv_bfloat162*)&g_ao_l[base + 2*tx]      = L01;
        *(__nv_bfloat162*)&g_ao_l[base + 2*tx + 32] = L23;
    }
}

// ---------------------------------------------------------------------------
extern "C" void kernel_launch(void* const* d_in, const int* in_sizes, int n_in,
                              void* d_out, int out_size)
{
    const float* q  = (const float*)d_in[0];
    const float* k  = (const float*)d_in[1];
    const float* v  = (const float*)d_in[2];
    const float* qw = (const float*)d_in[3];
    const float* qb = (const float*)d_in[4];
    const float* kw = (const float*)d_in[5];
    const float* kb = (const float*)d_in[6];
    const float* vw = (const float*)d_in[7];
    const float* vb = (const float*)d_in[8];
    const float* ow = (const float*)d_in[9];
    const float* ob = (const float*)d_in[10];
    float* out = (float*)d_out;

    cudaFuncSetAttribute(gemm_qkv,   cudaFuncAttributeMaxDynamicSharedMemorySize, SMEM_B);
    cudaFuncSetAttribute(gemm_o,     cudaFuncAttributeMaxDynamicSharedMemorySize, SMEM_B);
    cudaFuncSetAttribute(attn_kernel, cudaFuncAttributeMaxDynamicSharedMemorySize, ATT_SMEM);

    rope_table_kernel<<<64, 1024>>>();
    cvt_in<<<dim3(MROWS*DIM/4/256, 1, 3), 256>>>(q, k, v);
    cvt_w <<<dim3(DIM*DIM/4/256, 1, 4), 256>>>(qw, kw, vw, ow);
    gemm_qkv<<<dim3(DIM/128, MROWS/128, 3), 256, SMEM_B>>>(qb, kb, vb);
    attn_kernel<<<dim3(SEQ/64, NB*NH), 256, ATT_SMEM>>>();
    gemm_o<<<dim3(DIM/128, MROWS/128), 256, SMEM_B>>>(ob, out);
}

// round 9
// speedup vs baseline: 2.6775x; 1.5955x over previous
#include <cuda_runtime.h>
#include <cuda_bf16.h>
#include <cstdint>

#define NB   2
#define SEQ  2048
#define DIM  1024
#define NH   16
#define HD   64
#define MROWS (NB*SEQ)   // 4096

// ---------------------------------------------------------------------------
// Scratch (allocation-free rule: __device__ globals; device-code refs ONLY)
// ---------------------------------------------------------------------------
// projection A operands (hi/lo bf16 splits of inputs)
__device__ __nv_bfloat16 g_aq_h[MROWS*DIM], g_aq_l[MROWS*DIM];
__device__ __nv_bfloat16 g_ak_h[MROWS*DIM], g_ak_l[MROWS*DIM];
__device__ __nv_bfloat16 g_av_h[MROWS*DIM], g_av_l[MROWS*DIM];
// weights (hi/lo)
__device__ __nv_bfloat16 g_wq_h[DIM*DIM], g_wq_l[DIM*DIM];
__device__ __nv_bfloat16 g_wk_h[DIM*DIM], g_wk_l[DIM*DIM];
__device__ __nv_bfloat16 g_wv_h[DIM*DIM], g_wv_l[DIM*DIM];
__device__ __nv_bfloat16 g_wo_h[DIM*DIM], g_wo_l[DIM*DIM];
// attention operands produced by projections (bf16 hi/lo)
__device__ __nv_bfloat16 g_qh[NB*NH*SEQ*HD], g_ql[NB*NH*SEQ*HD];   // [B,H,S,hd] roped+scaled
__device__ __nv_bfloat16 g_kh[NB*NH*SEQ*HD], g_kl[NB*NH*SEQ*HD];   // [B,H,S,hd] roped
__device__ __nv_bfloat16 g_vth[NB*NH*HD*SEQ], g_vtl[NB*NH*HD*SEQ]; // [B,H,hd,S] transposed
// attention output (A operand of O-projection)
__device__ __nv_bfloat16 g_ao_h[MROWS*DIM], g_ao_l[MROWS*DIM];
__device__ float g_cos[SEQ*(HD/2)];
__device__ float g_sin[SEQ*(HD/2)];

// ---------------------------------------------------------------------------
// Baseline-PTX helpers (compute_103-safe)
// ---------------------------------------------------------------------------
__device__ __forceinline__ uint32_t smem_u32(const void* p) {
    uint32_t a;
    asm("{ .reg .u64 t; cvta.to.shared.u64 t, %1; cvt.u32.u64 %0, t; }" : "=r"(a) : "l"(p));
    return a;
}
__device__ __forceinline__ void cp16(uint32_t dst, const void* src) {
    asm volatile("cp.async.cg.shared.global [%0], [%1], 16;"
                 :: "r"(dst), "l"(__cvta_generic_to_global(src)) : "memory");
}
#define CP_COMMIT() asm volatile("cp.async.commit_group;" ::: "memory")
#define CP_WAIT(n)  asm volatile("cp.async.wait_group %0;" :: "n"(n) : "memory")

__device__ __forceinline__ uint32_t lds32(uint32_t a) {
    uint32_t v;
    asm volatile("ld.shared.b32 %0, [%1];" : "=r"(v) : "r"(a));
    return v;
}
__device__ __forceinline__ void mma16816(float* c, const uint32_t* a, uint32_t b0, uint32_t b1) {
    asm volatile("mma.sync.aligned.m16n8k16.row.col.f32.bf16.bf16.f32 "
                 "{%0,%1,%2,%3}, {%4,%5,%6,%7}, {%8,%9}, {%0,%1,%2,%3};"
                 : "+f"(c[0]), "+f"(c[1]), "+f"(c[2]), "+f"(c[3])
                 : "r"(a[0]), "r"(a[1]), "r"(a[2]), "r"(a[3]), "r"(b0), "r"(b1));
}
// split pair of floats into hi/lo bf16x2 registers (low halfword = first elem)
__device__ __forceinline__ void split2(float a, float b, uint32_t& hi, uint32_t& lo) {
    __nv_bfloat162 H = __floats2bfloat162_rn(a, b);
    float ra = a - __bfloat162float(H.x);
    float rb = b - __bfloat162float(H.y);
    __nv_bfloat162 L = __floats2bfloat162_rn(ra, rb);
    hi = *(uint32_t*)&H; lo = *(uint32_t*)&L;
}

// ---------------------------------------------------------------------------
// RoPE table — fp32 angle matching reference, DP range-reduction, fp32 sincos
// ---------------------------------------------------------------------------
__global__ void rope_table_kernel() {
    __shared__ float invs[32];
    int tid = threadIdx.x;
    if (tid < 32)
        invs[tid] = (float)pow(10000.0, -(double)tid / 32.0);
    __syncthreads();
    int i = blockIdx.x * blockDim.x + tid;
    int s = i >> 5;
    int p = i & 31;
    float ang = (float)s * invs[p];
    double ad = (double)ang;
    double k  = (double)__double2int_rn(ad * 0.15915494309189535);
    float r   = (float)(ad - k * 6.283185307179586);
    g_cos[i] = cosf(r);
    g_sin[i] = sinf(r);
}

// ---------------------------------------------------------------------------
// fp32 -> (hi, lo) bf16 splits for projection operands
// ---------------------------------------------------------------------------
__device__ __forceinline__ void split4(float4 v, __nv_bfloat16* hi, __nv_bfloat16* lo, int i) {
    uint32_t h01, l01, h23, l23;
    split2(v.x, v.y, h01, l01);
    split2(v.z, v.w, h23, l23);
    ((uint32_t*)hi)[2*i]   = h01;
    ((uint32_t*)hi)[2*i+1] = h23;
    ((uint32_t*)lo)[2*i]   = l01;
    ((uint32_t*)lo)[2*i+1] = l23;
}
__global__ void cvt_in(const float* __restrict__ q, const float* __restrict__ k,
                       const float* __restrict__ v) {
    int z = blockIdx.z;
    int i = blockIdx.x * blockDim.x + threadIdx.x;
    const float* src = (z == 0) ? q : (z == 1) ? k : v;
    __nv_bfloat16* hi = (z == 0) ? g_aq_h : (z == 1) ? g_ak_h : g_av_h;
    __nv_bfloat16* lo = (z == 0) ? g_aq_l : (z == 1) ? g_ak_l : g_av_l;
    split4(((const float4*)src)[i], hi, lo, i);
}
__global__ void cvt_w(const float* __restrict__ qw, const float* __restrict__ kw,
                      const float* __restrict__ vw, const float* __restrict__ ow) {
    int z = blockIdx.z;
    int i = blockIdx.x * blockDim.x + threadIdx.x;
    const float* src = (z == 0) ? qw : (z == 1) ? kw : (z == 2) ? vw : ow;
    __nv_bfloat16* hi = (z == 0) ? g_wq_h : (z == 1) ? g_wk_h : (z == 2) ? g_wv_h : g_wo_h;
    __nv_bfloat16* lo = (z == 0) ? g_wq_l : (z == 1) ? g_wk_l : (z == 2) ? g_wv_l : g_wo_l;
    split4(((const float4*)src)[i], hi, lo, i);
}

// ---------------------------------------------------------------------------
// mma.sync NT GEMM core (proven R7/R8): CTA 128x128, 8 warps, BK=32,
// 2-stage cp.async, explicit per-lane fragment loads, 3-term bf16 split.
// ---------------------------------------------------------------------------
#define BK        32
#define ROWPAD    40
#define OPBUF_B   (128*ROWPAD*2)
#define STAGE_B   (4*OPBUF_B)
#define SMEM_B    (2*STAGE_B)

__device__ __forceinline__ void gemm_core(
    const __nv_bfloat16* Ah, const __nv_bfloat16* Al,
    const __nv_bfloat16* Wh, const __nv_bfloat16* Wl,
    int row0, int col0, char* smem, uint32_t sb, float c[4][4][4])
{
    const int tid  = threadIdx.x;
    const int lane = tid & 31;
    const int wid  = tid >> 5;
    const int wm   = wid >> 2, wn = wid & 3;

    const int lr = tid >> 1, lh = tid & 1;
    const __nv_bfloat16* pa = Ah + (size_t)(row0 + lr) * DIM + lh*16;
    const __nv_bfloat16* pl = Al + (size_t)(row0 + lr) * DIM + lh*16;
    const __nv_bfloat16* pw = Wh + (size_t)(col0 + lr) * DIM + lh*16;
    const __nv_bfloat16* pm = Wl + (size_t)(col0 + lr) * DIM + lh*16;
    const uint32_t sdst = sb + lr*(ROWPAD*2) + lh*32;

    auto load_stage = [&](int ci, int st) {
        uint32_t d = sdst + st*STAGE_B;
        int ko = ci * BK;
        cp16(d,                    pa + ko);  cp16(d + 16,             pa + ko + 8);
        cp16(d + OPBUF_B,          pl + ko);  cp16(d + OPBUF_B + 16,   pl + ko + 8);
        cp16(d + 2*OPBUF_B,        pw + ko);  cp16(d + 2*OPBUF_B + 16, pw + ko + 8);
        cp16(d + 3*OPBUF_B,        pm + ko);  cp16(d + 3*OPBUF_B + 16, pm + ko + 8);
    };

    const int lr4 = lane >> 2;
    const int lk2 = (lane & 3) * 2;

    load_stage(0, 0);
    CP_COMMIT();

    const int NCHUNK = DIM / BK;
    for (int ci = 0; ci < NCHUNK; ci++) {
        if (ci + 1 < NCHUNK) { load_stage(ci + 1, (ci + 1) & 1); CP_COMMIT(); CP_WAIT(1); }
        else                 { CP_WAIT(0); }
        __syncthreads();

        const uint32_t sA   = sb + (ci & 1)*STAGE_B;
        const uint32_t sAlo = sA + OPBUF_B;
        const uint32_t sW   = sA + 2*OPBUF_B;
        const uint32_t sWlo = sA + 3*OPBUF_B;

        #pragma unroll
        for (int kk = 0; kk < 2; kk++) {
            const int c0 = kk*16 + lk2;
            uint32_t bh0[4], bh1[4], bl0[4], bl1[4];
            #pragma unroll
            for (int ni = 0; ni < 4; ni++) {
                const uint32_t wr = (uint32_t)(wn*32 + ni*8 + lr4) * (ROWPAD*2);
                bh0[ni] = lds32(sW   + wr + c0*2);
                bh1[ni] = lds32(sW   + wr + (c0+8)*2);
                bl0[ni] = lds32(sWlo + wr + c0*2);
                bl1[ni] = lds32(sWlo + wr + (c0+8)*2);
            }
            #pragma unroll
            for (int mi = 0; mi < 4; mi++) {
                const uint32_t ar0 = (uint32_t)(wm*64 + mi*16 + lr4) * (ROWPAD*2);
                const uint32_t ar8 = ar0 + 8*(ROWPAD*2);
                uint32_t ah[4], al[4];
                ah[0] = lds32(sA + ar0 + c0*2);
                ah[1] = lds32(sA + ar8 + c0*2);
                ah[2] = lds32(sA + ar0 + (c0+8)*2);
                ah[3] = lds32(sA + ar8 + (c0+8)*2);
                al[0] = lds32(sAlo + ar0 + c0*2);
                al[1] = lds32(sAlo + ar8 + c0*2);
                al[2] = lds32(sAlo + ar0 + (c0+8)*2);
                al[3] = lds32(sAlo + ar8 + (c0+8)*2);
                #pragma unroll
                for (int ni = 0; ni < 4; ni++) {
                    mma16816(c[mi][ni], ah, bh0[ni], bh1[ni]);
                    mma16816(c[mi][ni], ah, bl0[ni], bl1[ni]);
                    mma16816(c[mi][ni], al, bh0[ni], bh1[ni]);
                }
            }
        }
        __syncthreads();
    }
}

// Fused Q/K/V projection: z selects operands + epilogue.
// Q: +bias, *0.125, RoPE -> bf16 hi/lo [B,H,S,hd]
// K: +bias, RoPE        -> bf16 hi/lo [B,H,S,hd]
// V: +bias              -> bf16 hi/lo TRANSPOSED [B,H,hd,S]
__global__ void __launch_bounds__(256) gemm_qkv(
    const float* __restrict__ qb, const float* __restrict__ kb,
    const float* __restrict__ vb)
{
    extern __shared__ __align__(16) char smem[];
    const uint32_t sb = smem_u32(smem);
    const int z = blockIdx.z;
    const int row0 = (int)blockIdx.y << 7, col0 = (int)blockIdx.x << 7;

    const __nv_bfloat16* Ah = (z == 0) ? g_aq_h : (z == 1) ? g_ak_h : g_av_h;
    const __nv_bfloat16* Al = (z == 0) ? g_aq_l : (z == 1) ? g_ak_l : g_av_l;
    const __nv_bfloat16* Wh = (z == 0) ? g_wq_h : (z == 1) ? g_wk_h : g_wv_h;
    const __nv_bfloat16* Wl = (z == 0) ? g_wq_l : (z == 1) ? g_wk_l : g_wv_l;
    const float* bias = (z == 0) ? qb : (z == 1) ? kb : vb;

    float c[4][4][4];
    #pragma unroll
    for (int mi = 0; mi < 4; mi++)
        #pragma unroll
        for (int ni = 0; ni < 4; ni++)
            #pragma unroll
            for (int j = 0; j < 4; j++) c[mi][ni][j] = 0.f;

    gemm_core(Ah, Al, Wh, Wl, row0, col0, smem, sb, c);

    const int lane = threadIdx.x & 31, wid = threadIdx.x >> 5;
    const int wm = wid >> 2, wn = wid & 3;
    const int r_l = lane >> 2, c_l = (lane & 3)*2;
    #pragma unroll
    for (int mi = 0; mi < 4; mi++) {
        #pragma unroll
        for (int ni = 0; ni < 4; ni++) {
            const int n = col0 + wn*32 + ni*8 + c_l;
            float2 bv = *(const float2*)&bias[n];
            const int h = n >> 6, d0 = n & 63;
            #pragma unroll
            for (int hf = 0; hf < 2; hf++) {
                const int m = row0 + wm*64 + mi*16 + r_l + hf*8;
                const int b = m >> 11, sIdx = m & (SEQ - 1);
                const int bh = b*NH + h;
                float e = c[mi][ni][2*hf]   + bv.x;
                float o = c[mi][ni][2*hf+1] + bv.y;
                if (z <= 1) {
                    if (z == 0) { e *= 0.125f; o *= 0.125f; }
                    float cc = g_cos[sIdx*32 + (d0 >> 1)];
                    float ss = g_sin[sIdx*32 + (d0 >> 1)];
                    float re = e*cc - o*ss;
                    float im = e*ss + o*cc;
                    uint32_t hi, lo;
                    split2(re, im, hi, lo);
                    size_t idx = ((size_t)bh*SEQ + sIdx)*HD + d0;
                    if (z == 0) {
                        *(uint32_t*)&g_qh[idx] = hi;
                        *(uint32_t*)&g_ql[idx] = lo;
                    } else {
                        *(uint32_t*)&g_kh[idx] = hi;
                        *(uint32_t*)&g_kl[idx] = lo;
                    }
                } else {
                    // V transposed store [B,H,hd,S]
                    __nv_bfloat16 he = __float2bfloat16(e);
                    __nv_bfloat16 ho = __float2bfloat16(o);
                    size_t i0 = ((size_t)bh*HD + d0)*SEQ + sIdx;
                    g_vth[i0]       = he;
                    g_vth[i0 + SEQ] = ho;
                    g_vtl[i0]       = __float2bfloat16(e - __bfloat162float(he));
                    g_vtl[i0 + SEQ] = __float2bfloat16(o - __bfloat162float(ho));
                }
            }
        }
    }
}

// Output projection GEMM: A = g_ao pair, W = g_wo pair -> Cout fp32.
__global__ void __launch_bounds__(256) gemm_o(
    const float* __restrict__ bias, float* __restrict__ Cout)
{
    extern __shared__ __align__(16) char smem[];
    const uint32_t sb = smem_u32(smem);
    const int row0 = (int)blockIdx.y << 7, col0 = (int)blockIdx.x << 7;

    float c[4][4][4];
    #pragma unroll
    for (int mi = 0; mi < 4; mi++)
        #pragma unroll
        for (int ni = 0; ni < 4; ni++)
            #pragma unroll
            for (int j = 0; j < 4; j++) c[mi][ni][j] = 0.f;

    gemm_core(g_ao_h, g_ao_l, g_wo_h, g_wo_l, row0, col0, smem, sb, c);

    const int lane = threadIdx.x & 31, wid = threadIdx.x >> 5;
    const int wm = wid >> 2, wn = wid & 3;
    const int r_l = lane >> 2, c_l = (lane & 3)*2;
    #pragma unroll
    for (int mi = 0; mi < 4; mi++) {
        #pragma unroll
        for (int ni = 0; ni < 4; ni++) {
            const int n = col0 + wn*32 + ni*8 + c_l;
            float2 bv = *(const float2*)&bias[n];
            #pragma unroll
            for (int hf = 0; hf < 2; hf++) {
                const int m = row0 + wm*64 + mi*16 + r_l + hf*8;
                *(float2*)&Cout[(size_t)m*DIM + n] =
                    make_float2(c[mi][ni][2*hf] + bv.x, c[mi][ni][2*hf+1] + bv.y);
            }
        }
    }
}

// ---------------------------------------------------------------------------
// Flash attention on mma.sync. CTA = 128 q-rows x (bh); warp = 16 q-rows,
// full 64-col kv tile (softmax warp-local). 32 kv tiles, K/V^T hi/lo bf16 in
// smem double-buffered via cp.async. P stays in registers (S C-frag == P
// A-frag layout). 3-term hi/lo split on both QK^T and PV.
// smem pitch 72 bf16 (144B): rows hit distinct banks for frag loads.
// ---------------------------------------------------------------------------
#define AT_PITCH  72
#define AT_BUF    (64*AT_PITCH*2)    // 9216 B per operand tile
#define AT_STAGE  (4*AT_BUF)         // 36864 B
#define AT_SMEM   (2*AT_STAGE)       // 73728 B

__global__ void __launch_bounds__(256) attn_mma() {
    extern __shared__ __align__(16) char smem[];
    const uint32_t sb = smem_u32(smem);

    const int tid = threadIdx.x, lane = tid & 31, wid = tid >> 5;
    const int lr4 = lane >> 2, lk2 = (lane & 3) * 2;
    const int qt = blockIdx.x, bh = blockIdx.y;

    // Q fragments (registers, loaded once from gmem)
    const __nv_bfloat16* Qhp = g_qh + ((size_t)bh*SEQ + qt*128 + wid*16)*HD;
    const __nv_bfloat16* Qlp = g_ql + ((size_t)bh*SEQ + qt*128 + wid*16)*HD;
    uint32_t qh[4][4], ql[4][4];
    #pragma unroll
    for (int kc = 0; kc < 4; kc++) {
        int c0 = kc*16 + lk2;
        qh[kc][0] = *(const uint32_t*)(Qhp + (size_t)lr4*HD + c0);
        qh[kc][1] = *(const uint32_t*)(Qhp + (size_t)(lr4+8)*HD + c0);
        qh[kc][2] = *(const uint32_t*)(Qhp + (size_t)lr4*HD + c0 + 8);
        qh[kc][3] = *(const uint32_t*)(Qhp + (size_t)(lr4+8)*HD + c0 + 8);
        ql[kc][0] = *(const uint32_t*)(Qlp + (size_t)lr4*HD + c0);
        ql[kc][1] = *(const uint32_t*)(Qlp + (size_t)(lr4+8)*HD + c0);
        ql[kc][2] = *(const uint32_t*)(Qlp + (size_t)lr4*HD + c0 + 8);
        ql[kc][3] = *(const uint32_t*)(Qlp + (size_t)(lr4+8)*HD + c0 + 8);
    }

    // tile loader: buffers {Kh, Kl, Vth, Vtl}, 512 16B-chunks each
    auto loadKV = [&](int it, int st) {
        int kt = it * 64;
        uint32_t base = sb + st*AT_STAGE;
        #pragma unroll
        for (int j = 0; j < 8; j++) {
            int idx = tid*8 + j;
            int bufi = idx >> 9, row = (idx >> 3) & 63, ch = idx & 7;
            uint32_t dst = base + bufi*AT_BUF + row*(AT_PITCH*2) + ch*16;
            const __nv_bfloat16* src;
            if (bufi == 0)      src = g_kh  + ((size_t)bh*SEQ + kt + row)*HD + ch*8;
            else if (bufi == 1) src = g_kl  + ((size_t)bh*SEQ + kt + row)*HD + ch*8;
            else if (bufi == 2) src = g_vth + ((size_t)bh*HD + row)*SEQ + kt + ch*8;
            else                src = g_vtl + ((size_t)bh*HD + row)*SEQ + kt + ch*8;
            cp16(dst, src);
        }
    };
    loadKV(0, 0);
    CP_COMMIT();

    float o[8][4];
    #pragma unroll
    for (int nf = 0; nf < 8; nf++)
        #pragma unroll
        for (int j = 0; j < 4; j++) o[nf][j] = 0.f;
    float m0 = -1e30f, m1 = -1e30f, l0 = 0.f, l1 = 0.f;

    for (int it = 0; it < 32; it++) {
        CP_WAIT(0);
        __syncthreads();
        if (it + 1 < 32) { loadKV(it + 1, (it + 1) & 1); CP_COMMIT(); }

        const uint32_t Khs = sb + (it & 1)*AT_STAGE;
        const uint32_t Kls = Khs + AT_BUF;
        const uint32_t Vhs = Khs + 2*AT_BUF;
        const uint32_t Vls = Khs + 3*AT_BUF;

        // S = Q K^T  (scores; Q pre-scaled + roped)
        float s[8][4];
        #pragma unroll
        for (int nf = 0; nf < 8; nf++)
            #pragma unroll
            for (int j = 0; j < 4; j++) s[nf][j] = 0.f;
        #pragma unroll
        for (int kc = 0; kc < 4; kc++) {
            const uint32_t cb = (kc*16 + lk2)*2;
            #pragma unroll
            for (int nf = 0; nf < 8; nf++) {
                const uint32_t rb = (uint32_t)(nf*8 + lr4)*(AT_PITCH*2);
                uint32_t kh0 = lds32(Khs + rb + cb);
                uint32_t kh1 = lds32(Khs + rb + cb + 16);
                uint32_t kl0 = lds32(Kls + rb + cb);
                uint32_t kl1 = lds32(Kls + rb + cb + 16);
                mma16816(s[nf], qh[kc], kh0, kh1);
                mma16816(s[nf], qh[kc], kl0, kl1);
                mma16816(s[nf], ql[kc], kh0, kh1);
            }
        }

        // online softmax (rows lr4 and lr4+8; stats across lane&3 group)
        float mx0 = -1e30f, mx1 = -1e30f;
        #pragma unroll
        for (int nf = 0; nf < 8; nf++) {
            mx0 = fmaxf(mx0, fmaxf(s[nf][0], s[nf][1]));
            mx1 = fmaxf(mx1, fmaxf(s[nf][2], s[nf][3]));
        }
        mx0 = fmaxf(mx0, __shfl_xor_sync(0xffffffffu, mx0, 1));
        mx0 = fmaxf(mx0, __shfl_xor_sync(0xffffffffu, mx0, 2));
        mx1 = fmaxf(mx1, __shfl_xor_sync(0xffffffffu, mx1, 1));
        mx1 = fmaxf(mx1, __shfl_xor_sync(0xffffffffu, mx1, 2));
        float mn0 = fmaxf(m0, mx0), mn1 = fmaxf(m1, mx1);
        float alpha0 = __expf(m0 - mn0), alpha1 = __expf(m1 - mn1);
        m0 = mn0; m1 = mn1;

        uint32_t ph[4][4], pl[4][4];
        float sum0 = 0.f, sum1 = 0.f;
        #pragma unroll
        for (int nf = 0; nf < 8; nf++) {
            float p0 = __expf(s[nf][0] - mn0), p1 = __expf(s[nf][1] - mn0);
            float p2 = __expf(s[nf][2] - mn1), p3 = __expf(s[nf][3] - mn1);
            sum0 += p0 + p1; sum1 += p2 + p3;
            const int kcc = nf >> 1, ps = (nf & 1)*2;
            split2(p0, p1, ph[kcc][ps],   pl[kcc][ps]);
            split2(p2, p3, ph[kcc][ps+1], pl[kcc][ps+1]);
        }
        sum0 += __shfl_xor_sync(0xffffffffu, sum0, 1);
        sum0 += __shfl_xor_sync(0xffffffffu, sum0, 2);
        sum1 += __shfl_xor_sync(0xffffffffu, sum1, 1);
        sum1 += __shfl_xor_sync(0xffffffffu, sum1, 2);
        l0 = l0*alpha0 + sum0;
        l1 = l1*alpha1 + sum1;
        #pragma unroll
        for (int nf = 0; nf < 8; nf++) {
            o[nf][0] *= alpha0; o[nf][1] *= alpha0;
            o[nf][2] *= alpha1; o[nf][3] *= alpha1;
        }

        // O += P V  (B = V^T [d][kv] in smem)
        #pragma unroll
        for (int kc = 0; kc < 4; kc++) {
            const uint32_t cb = (kc*16 + lk2)*2;
            #pragma unroll
            for (int nf = 0; nf < 8; nf++) {
                const uint32_t rb = (uint32_t)(nf*8 + lr4)*(AT_PITCH*2);
                uint32_t vh0 = lds32(Vhs + rb + cb);
                uint32_t vh1 = lds32(Vhs + rb + cb + 16);
                uint32_t vl0 = lds32(Vls + rb + cb);
                uint32_t vl1 = lds32(Vls + rb + cb + 16);
                mma16816(o[nf], ph[kc], vh0, vh1);
                mma16816(o[nf], ph[kc], vl0, vl1);
                mma16816(o[nf], pl[kc], vh0, vh1);
            }
        }
    }

    // epilogue: normalize rows, write [B,S,H,hd] bf16 hi/lo for O-proj
    const float inv0 = 1.0f / l0, inv1 = 1.0f / l1;
    const int b = bh >> 4, h = bh & 15;
    const int s0 = qt*128 + wid*16 + lr4, s1 = s0 + 8;
    const size_t base0 = ((size_t)(b*SEQ + s0)*NH + h)*HD;
    const size_t base1 = ((size_t)(b*SEQ + s1)*NH + h)*HD;
    #pragma unroll
    for (int nf = 0; nf < 8; nf++) {
        const int d = nf*8 + lk2;
        uint32_t hi, lo;
        split2(o[nf][0]*inv0, o[nf][1]*inv0, hi, lo);
        *(uint32_t*)&g_ao_h[base0 + d] = hi;
        *(uint32_t*)&g_ao_l[base0 + d] = lo;
        split2(o[nf][2]*inv1, o[nf][3]*inv1, hi, lo);
        *(uint32_t*)&g_ao_h[base1 + d] = hi;
        *(uint32_t*)&g_ao_l[base1 + d] = lo;
    }
}

// ---------------------------------------------------------------------------
extern "C" void kernel_launch(void* const* d_in, const int* in_sizes, int n_in,
                              void* d_out, int out_size)
{
    const float* q  = (const float*)d_in[0];
    const float* k  = (const float*)d_in[1];
    const float* v  = (const float*)d_in[2];
    const float* qw = (const float*)d_in[3];
    const float* qb = (const float*)d_in[4];
    const float* kw = (const float*)d_in[5];
    const float* kb = (const float*)d_in[6];
    const float* vw = (const float*)d_in[7];
    const float* vb = (const float*)d_in[8];
    const float* ow = (const float*)d_in[9];
    const float* ob = (const float*)d_in[10];
    float* out = (float*)d_out;

    cudaFuncSetAttribute(gemm_qkv, cudaFuncAttributeMaxDynamicSharedMemorySize, SMEM_B);
    cudaFuncSetAttribute(gemm_o,   cudaFuncAttributeMaxDynamicSharedMemorySize, SMEM_B);
    cudaFuncSetAttribute(attn_mma, cudaFuncAttributeMaxDynamicSharedMemorySize, AT_SMEM);

    rope_table_kernel<<<64, 1024>>>();
    cvt_in<<<dim3(MROWS*DIM/4/256, 1, 3), 256>>>(q, k, v);
    cvt_w <<<dim3(DIM*DIM/4/256, 1, 4), 256>>>(qw, kw, vw, ow);
    gemm_qkv<<<dim3(DIM/128, MROWS/128, 3), 256, SMEM_B>>>(qb, kb, vb);
    attn_mma<<<dim3(SEQ/128, NB*NH), 256, AT_SMEM>>>();
    gemm_o<<<dim3(DIM/128, MROWS/128), 256, SMEM_B>>>(ob, out);
}